// round 1
// baseline (speedup 1.0000x reference)
#include <cuda_runtime.h>

#define WIDTH  1024
#define HEIGHT 1024

// Per-block partial sums (one per image row). 32 batches * 1024 rows = 32768.
// Sized with headroom in case of shape variants up to 64 batches.
__device__ float g_partials[65536];

// One block per image row. 256 threads * 4 pixels = 1024 = WIDTH.
// Binary-mask morphology trick: boundary(x,y) <=> the clamped 3x3 window sum
// is strictly between 0 and 9 (window of exact 0.0/1.0 floats sums exactly).
// BCE with t in {0,1}: bce = -log(t ? p : 1-p)   (single __logf per pixel).
__global__ void __launch_bounds__(256)
loss_kernel(const float* __restrict__ pred, const float* __restrict__ tgt)
{
    const int row = blockIdx.x;           // global row index over (B*H)
    const int y   = row & (HEIGHT - 1);   // row within image
    const int c   = threadIdx.x << 2;     // first of 4 columns for this thread

    const size_t row_off = (size_t)row * WIDTH;
    const float* r1 = tgt + row_off;
    const float* r0 = (y == 0)          ? r1 : r1 - WIDTH;   // clamp top
    const float* r2 = (y == HEIGHT - 1) ? r1 : r1 + WIDTH;   // clamp bottom

    // Vectorized loads of the 3 target rows and the pred row.
    const float4 a0 = *reinterpret_cast<const float4*>(r0 + c);
    const float4 a1 = *reinterpret_cast<const float4*>(r1 + c);
    const float4 a2 = *reinterpret_cast<const float4*>(r2 + c);
    const float4 p  = *reinterpret_cast<const float4*>(pred + row_off + c);

    // Column-clamped halo samples.
    const int cl = (c == 0) ? 0 : c - 1;
    const int cr = (c + 4 >= WIDTH) ? (WIDTH - 1) : (c + 4);
    const float vl = r0[cl] + r1[cl] + r2[cl];
    const float vr = r0[cr] + r1[cr] + r2[cr];

    // Separable: vertical 3-sums per column, then horizontal 3-sums.
    const float v0 = a0.x + a1.x + a2.x;
    const float v1 = a0.y + a1.y + a2.y;
    const float v2 = a0.z + a1.z + a2.z;
    const float v3 = a0.w + a1.w + a2.w;

    const float s0 = vl + v0 + v1;
    const float s1 = v0 + v1 + v2;
    const float s2 = v1 + v2 + v3;
    const float s3 = v2 + v3 + vr;

    float acc = 0.0f;   // accumulates +w*log(arg); loss term is the negation

#define PIX(S, T, P)                                                      \
    do {                                                                  \
        const float arg = ((T) > 0.5f) ? (P) : (1.0f - (P));              \
        const float w   = ((S) > 0.5f && (S) < 8.5f) ? 3.0f : 1.0f;       \
        acc = fmaf(w, __logf(arg), acc);                                  \
    } while (0)

    PIX(s0, a1.x, p.x);
    PIX(s1, a1.y, p.y);
    PIX(s2, a1.z, p.z);
    PIX(s3, a1.w, p.w);
#undef PIX

    // Block reduction: warp shuffle, then 8 warp leaders through smem.
    #pragma unroll
    for (int o = 16; o > 0; o >>= 1)
        acc += __shfl_xor_sync(0xffffffffu, acc, o);

    __shared__ float sacc[8];
    const int wid  = threadIdx.x >> 5;
    const int lane = threadIdx.x & 31;
    if (lane == 0) sacc[wid] = acc;
    __syncthreads();
    if (threadIdx.x == 0) {
        float s = 0.0f;
        #pragma unroll
        for (int i = 0; i < 8; i++) s += sacc[i];
        g_partials[row] = -s;   // negate here: loss = -sum(w*log(arg))
    }
}

// Deterministic final reduction of per-row partials in double precision.
__global__ void __launch_bounds__(256)
finalize_kernel(float* __restrict__ out, int n_rows, double inv_n)
{
    double s = 0.0;
    for (int i = threadIdx.x; i < n_rows; i += 256)
        s += (double)g_partials[i];

    __shared__ double sd[256];
    sd[threadIdx.x] = s;
    __syncthreads();
    #pragma unroll
    for (int o = 128; o > 0; o >>= 1) {
        if (threadIdx.x < o) sd[threadIdx.x] += sd[threadIdx.x + o];
        __syncthreads();
    }
    if (threadIdx.x == 0)
        out[0] = (float)(sd[0] * inv_n);
}

extern "C" void kernel_launch(void* const* d_in, const int* in_sizes, int n_in,
                              void* d_out, int out_size)
{
    const float* pred = (const float*)d_in[0];
    const float* tgt  = (const float*)d_in[1];
    const int n    = in_sizes[0];          // total elements (B*1*H*W)
    const int rows = n / WIDTH;            // B*H

    loss_kernel<<<rows, 256>>>(pred, tgt);
    finalize_kernel<<<1, 256>>>((float*)d_out, rows, 1.0 / (double)n);
}

// round 2
// speedup vs baseline: 1.4272x; 1.4272x over previous
#include <cuda_runtime.h>

#define WIDTH  1024
#define HEIGHT 1024
#define RPB    8          // rows per block (must divide HEIGHT)

// One partial per block-strip. 32*1024/8 = 4096 for the nominal shape;
// headroom for variants.
__device__ float g_partials[65536];

struct RowData {
    float4 v;      // 4 target values at columns c..c+3
    float  hl, hr; // column halo (c-1 clamped, c+4 clamped)
};

__device__ __forceinline__ RowData load_row(const float* __restrict__ r,
                                            int c, int cl, int cr)
{
    RowData d;
    d.v  = *reinterpret_cast<const float4*>(r + c);
    d.hl = r[cl];
    d.hr = r[cr];
    return d;
}

// Each block handles an 8-row strip of one image. The 3-row target window
// rolls through registers, so each target row is loaded once (plus strip
// halo rows), instead of 3x.
// Binary-mask morphology: boundary <=> clamped 3x3 window sum in (0,9).
// BCE with t in {0,1}: bce = -log(t ? p : 1-p)  -> one __logf per pixel.
__global__ void __launch_bounds__(256)
loss_kernel(const float* __restrict__ pred, const float* __restrict__ tgt)
{
    const int strip = blockIdx.x;
    const int row0  = strip * RPB;          // global row over (B*H)
    const int y0    = row0 & (HEIGHT - 1);  // row within image (strip never crosses images)

    const int c  = threadIdx.x << 2;
    const int cl = (c == 0) ? 0 : c - 1;
    const int cr = (c + 4 >= WIDTH) ? (WIDTH - 1) : (c + 4);

    const float* tbase = tgt  + (size_t)row0 * WIDTH;
    const float* pbase = pred + (size_t)row0 * WIDTH;

    // Prime the rolling window: rows y0-1 (clamped) and y0.
    RowData a_prev = load_row((y0 == 0) ? tbase : tbase - WIDTH, c, cl, cr);
    RowData a_cur  = load_row(tbase, c, cl, cr);

    float acc = 0.0f;   // accumulates +w*log(arg); negated at the end

    #pragma unroll
    for (int i = 0; i < RPB; i++) {
        const int y = y0 + i;
        const float* trow_next = (y == HEIGHT - 1) ? tbase + (size_t)i * WIDTH
                                                   : tbase + (size_t)(i + 1) * WIDTH;
        const RowData a_next = load_row(trow_next, c, cl, cr);
        const float4  p = *reinterpret_cast<const float4*>(pbase + (size_t)i * WIDTH + c);

        // Vertical 3-sums per column, then horizontal 3-sums.
        const float v0 = a_prev.v.x + a_cur.v.x + a_next.v.x;
        const float v1 = a_prev.v.y + a_cur.v.y + a_next.v.y;
        const float v2 = a_prev.v.z + a_cur.v.z + a_next.v.z;
        const float v3 = a_prev.v.w + a_cur.v.w + a_next.v.w;
        const float vl = a_prev.hl  + a_cur.hl  + a_next.hl;
        const float vr = a_prev.hr  + a_cur.hr  + a_next.hr;

        const float s0 = vl + v0 + v1;
        const float s1 = v0 + v1 + v2;
        const float s2 = v1 + v2 + v3;
        const float s3 = v2 + v3 + vr;

#define PIX(S, T, P)                                                      \
        do {                                                              \
            const float arg = ((T) > 0.5f) ? (P) : (1.0f - (P));          \
            const float w   = ((S) > 0.5f && (S) < 8.5f) ? 3.0f : 1.0f;   \
            acc = fmaf(w, __logf(arg), acc);                              \
        } while (0)

        PIX(s0, a_cur.v.x, p.x);
        PIX(s1, a_cur.v.y, p.y);
        PIX(s2, a_cur.v.z, p.z);
        PIX(s3, a_cur.v.w, p.w);
#undef PIX

        a_prev = a_cur;
        a_cur  = a_next;
    }

    // Block reduction: warp shuffle, then 8 warp leaders through smem.
    #pragma unroll
    for (int o = 16; o > 0; o >>= 1)
        acc += __shfl_xor_sync(0xffffffffu, acc, o);

    __shared__ float sacc[8];
    const int wid  = threadIdx.x >> 5;
    const int lane = threadIdx.x & 31;
    if (lane == 0) sacc[wid] = acc;
    __syncthreads();
    if (threadIdx.x == 0) {
        float s = 0.0f;
        #pragma unroll
        for (int i = 0; i < 8; i++) s += sacc[i];
        g_partials[strip] = -s;
    }
}

// Deterministic final reduction (double precision), vectorized loads,
// independent accumulators for ILP.
__global__ void __launch_bounds__(256)
finalize_kernel(float* __restrict__ out, int n_part, double inv_n)
{
    const int n4 = n_part >> 2;   // n_part divisible by 4 (grid is)
    double s0 = 0.0, s1 = 0.0;
    for (int i = threadIdx.x; i < n4; i += 256) {
        const float4 v = reinterpret_cast<const float4*>(g_partials)[i];
        s0 += (double)v.x + (double)v.y;
        s1 += (double)v.z + (double)v.w;
    }
    double s = s0 + s1;

    __shared__ double sd[256];
    sd[threadIdx.x] = s;
    __syncthreads();
    #pragma unroll
    for (int o = 128; o > 0; o >>= 1) {
        if (threadIdx.x < o) sd[threadIdx.x] += sd[threadIdx.x + o];
        __syncthreads();
    }
    if (threadIdx.x == 0)
        out[0] = (float)(sd[0] * inv_n);
}

extern "C" void kernel_launch(void* const* d_in, const int* in_sizes, int n_in,
                              void* d_out, int out_size)
{
    const float* pred = (const float*)d_in[0];
    const float* tgt  = (const float*)d_in[1];
    const int n      = in_sizes[0];        // B*1*H*W
    const int rows   = n / WIDTH;          // B*H
    const int strips = rows / RPB;

    loss_kernel<<<strips, 256>>>(pred, tgt);
    finalize_kernel<<<1, 256>>>((float*)d_out, strips, 1.0 / (double)n);
}